// round 8
// baseline (speedup 1.0000x reference)
#include <cuda_runtime.h>
#include <cstdint>

typedef unsigned long long ULL;

#define B_    8
#define S_    4096
#define Hd    512
#define KD    512
#define NC    1024            // 2*H output cols of GEMM
#define Mrows 32768           // B_*S_
#define CH    32              // scan chunks per sequence
#define CL    128             // S_/CH
#define NOUT  16777216        // Mrows*Hd  (main output elements)

// ---------------- scratch (device globals; no allocations allowed) ----------
__device__ float  g_GH[(size_t)Mrows * NC];    // raw gemm output   128 MB
__device__ float2 g_AV[(size_t)Mrows * Hd];    // (a, v) pairs      128 MB
__device__ float  g_H0[(size_t)Mrows * Hd];    // layer-0 output     64 MB
__device__ float2 g_carry[B_ * CH * Hd];
__device__ float  g_hstart[B_ * CH * Hd];

// ---------------- packed fp32x2 helpers (Blackwell FFMA2 path) --------------
__device__ __forceinline__ ULL pack2(float x, float y) {
    ULL r; unsigned lo = __float_as_uint(x), hi = __float_as_uint(y);
    asm("mov.b64 %0, {%1, %2};" : "=l"(r) : "r"(lo), "r"(hi));
    return r;
}
__device__ __forceinline__ float2 unpack2(ULL v) {
    unsigned lo, hi;
    asm("mov.b64 {%0, %1}, %2;" : "=r"(lo), "=r"(hi) : "l"(v));
    return make_float2(__uint_as_float(lo), __uint_as_float(hi));
}
__device__ __forceinline__ ULL ffma2(ULL a, ULL b, ULL c) {
    ULL d;
    asm("fma.rn.f32x2 %0, %1, %2, %3;" : "=l"(d) : "l"(a), "l"(b), "l"(c));
    return d;
}

// ---------------- SGEMM: C[m,n] = sum_k A[m,k]*W[n,k] + bias[n] -------------
// A: [32768, 512] row-major (x or g_H0), W: [1024, 512] row-major.
// 128x128 tile, BK=16, 256 threads, 8x8 per thread, f32x2 accumulators
// paired along n, double-buffered smem.
#define BM 128
#define BN 128
#define BK 16
#define LDS_ 132   // padded row to reduce STS bank conflicts

__global__ __launch_bounds__(256) void sgemm_kernel(int layer,
                                                    const float* __restrict__ Xin,
                                                    const float* __restrict__ W,
                                                    const float* __restrict__ bias)
{
    __shared__ __align__(16) float As[2][BK][LDS_];
    __shared__ __align__(16) float Bs[2][BK][LDS_];

    const float* Ain = layer ? g_H0 : Xin;

    const int bn = blockIdx.x;
    const int bm = blockIdx.y;
    const int t  = threadIdx.x;
    const int tx = t & 15;
    const int ty = t >> 4;

    // loading: each thread brings one float4 for rows r0 and r0+64, k-offset q4
    const int r0 = t >> 2;
    const int q4 = (t & 3) << 2;

    const float* aP0 = Ain + (size_t)(bm * BM + r0) * KD + q4;
    const float* aP1 = aP0 + (size_t)64 * KD;
    const float* bP0 = W   + (size_t)(bn * BN + r0) * KD + q4;
    const float* bP1 = bP0 + (size_t)64 * KD;

    ULL acc[8][4];
#pragma unroll
    for (int m = 0; m < 8; ++m)
#pragma unroll
        for (int j = 0; j < 4; ++j) acc[m][j] = 0ULL;

    auto stq = [&](float* s, int r, float4 v) {
        s[(q4 + 0) * LDS_ + r] = v.x;
        s[(q4 + 1) * LDS_ + r] = v.y;
        s[(q4 + 2) * LDS_ + r] = v.z;
        s[(q4 + 3) * LDS_ + r] = v.w;
    };

    // prologue: tile 0
    float4 ra0 = *(const float4*)(aP0);
    float4 ra1 = *(const float4*)(aP1);
    float4 rb0 = *(const float4*)(bP0);
    float4 rb1 = *(const float4*)(bP1);
    stq(&As[0][0][0], r0,      ra0);
    stq(&As[0][0][0], r0 + 64, ra1);
    stq(&Bs[0][0][0], r0,      rb0);
    stq(&Bs[0][0][0], r0 + 64, rb1);
    __syncthreads();

    int buf = 0;
#pragma unroll 1
    for (int kt = 0; kt < KD / BK; ++kt) {
        if (kt < KD / BK - 1) {
            ra0 = *(const float4*)(aP0 + (kt + 1) * BK);
            ra1 = *(const float4*)(aP1 + (kt + 1) * BK);
            rb0 = *(const float4*)(bP0 + (kt + 1) * BK);
            rb1 = *(const float4*)(bP1 + (kt + 1) * BK);
        }
        const float* pa = &As[buf][0][0];
        const float* pb = &Bs[buf][0][0];
#pragma unroll
        for (int k = 0; k < BK; ++k) {
            float4 a0 = *(const float4*)(pa + k * LDS_ + ty * 8);
            float4 a1 = *(const float4*)(pa + k * LDS_ + ty * 8 + 4);
            float4 b0 = *(const float4*)(pb + k * LDS_ + tx * 8);
            float4 b1 = *(const float4*)(pb + k * LDS_ + tx * 8 + 4);
            ULL bp0 = pack2(b0.x, b0.y), bp1 = pack2(b0.z, b0.w);
            ULL bp2 = pack2(b1.x, b1.y), bp3 = pack2(b1.z, b1.w);
            float am[8] = {a0.x, a0.y, a0.z, a0.w, a1.x, a1.y, a1.z, a1.w};
#pragma unroll
            for (int m = 0; m < 8; ++m) {
                ULL a2 = pack2(am[m], am[m]);
                acc[m][0] = ffma2(a2, bp0, acc[m][0]);
                acc[m][1] = ffma2(a2, bp1, acc[m][1]);
                acc[m][2] = ffma2(a2, bp2, acc[m][2]);
                acc[m][3] = ffma2(a2, bp3, acc[m][3]);
            }
        }
        if (kt < KD / BK - 1) {
            float* sa = &As[buf ^ 1][0][0];
            float* sb = &Bs[buf ^ 1][0][0];
            stq(sa, r0,      ra0);
            stq(sa, r0 + 64, ra1);
            stq(sb, r0,      rb0);
            stq(sb, r0 + 64, rb1);
            __syncthreads();
            buf ^= 1;
        }
    }

    // epilogue: add bias, write to g_GH
    const int gm = bm * BM + ty * 8;
    const int gn = bn * BN + tx * 8;
    float4 bv0 = *(const float4*)(bias + gn);
    float4 bv1 = *(const float4*)(bias + gn + 4);
#pragma unroll
    for (int m = 0; m < 8; ++m) {
        float2 v0 = unpack2(acc[m][0]);
        float2 v1 = unpack2(acc[m][1]);
        float2 v2 = unpack2(acc[m][2]);
        float2 v3 = unpack2(acc[m][3]);
        float4 o0 = make_float4(v0.x + bv0.x, v0.y + bv0.y, v1.x + bv0.z, v1.y + bv0.w);
        float4 o1 = make_float4(v2.x + bv1.x, v2.y + bv1.y, v3.x + bv1.z, v3.y + bv1.w);
        float* dst = g_GH + (size_t)(gm + m) * NC + gn;
        *(float4*)(dst)     = o0;
        *(float4*)(dst + 4) = o1;
    }
}

// ---------------- elementwise: gate/hidden -> (a, v) ------------------------
// a = sigmoid(-gate) = exp(log_coeffs); v = sigmoid(gate) * g(hidden)
// g(x) = x + 0.5 (x>=0) else sigmoid(x). All in linear space (positive terms).
__global__ void prep_kernel()
{
    size_t i = (size_t)blockIdx.x * blockDim.x + threadIdx.x;   // over Mrows*Hd
    int    h = (int)(i & (Hd - 1));
    size_t m = i >> 9;
    float gate = g_GH[m * NC + h];
    float hid  = g_GH[m * NC + Hd + h];
    float z = 1.0f / (1.0f + expf(-gate));
    float a = 1.0f / (1.0f + expf(gate));
    float g = (hid >= 0.0f) ? (hid + 0.5f) : (1.0f / (1.0f + expf(-hid)));
    g_AV[i] = make_float2(a, z * g);
}

// ---------------- chunked scan: h_t = a_t*h_{t-1} + v_t,  h_{-1} = 0.5 ------
// Phase A: per-(b,chunk,h) aggregate (P = prod a, Q = recurrence from 0)
__global__ void scanA_kernel()
{
    int h = threadIdx.x;
    int c = blockIdx.x & (CH - 1);
    int b = blockIdx.x >> 5;
    const float2* p = g_AV + ((size_t)b * S_ + (size_t)c * CL) * Hd + h;
    float P = 1.0f, Q = 0.0f;
#pragma unroll 4
    for (int s = 0; s < CL; ++s) {
        float2 av = p[(size_t)s * Hd];
        Q = fmaf(av.x, Q, av.y);
        P *= av.x;
    }
    g_carry[(b * CH + c) * Hd + h] = make_float2(P, Q);
}

// Phase B: serial scan over the CH chunk aggregates -> chunk-start states
__global__ void scanB_kernel()
{
    int h = threadIdx.x;
    int b = blockIdx.x;
    float hc = 0.5f;
#pragma unroll
    for (int c = 0; c < CH; ++c) {
        int idx = (b * CH + c) * Hd + h;
        g_hstart[idx] = hc;
        float2 pq = g_carry[idx];
        hc = fmaf(pq.x, hc, pq.y);
    }
}

// Phase C: replay chunks from start states, write outputs
__global__ void scanC_kernel(int layer, float* __restrict__ Oout)
{
    int h = threadIdx.x;
    int c = blockIdx.x & (CH - 1);
    int b = blockIdx.x >> 5;
    float* O = layer ? Oout : g_H0;
    float hc = g_hstart[(b * CH + c) * Hd + h];
    const float2* p = g_AV + ((size_t)b * S_ + (size_t)c * CL) * Hd + h;
    float*        o = O    + ((size_t)b * S_ + (size_t)c * CL) * Hd + h;
#pragma unroll 4
    for (int s = 0; s < CL; ++s) {
        float2 av = p[(size_t)s * Hd];
        hc = fmaf(av.x, hc, av.y);
        o[(size_t)s * Hd] = hc;
    }
}

// ---------------- tail: stacked next_hidden (2, B, 1, H) --------------------
__global__ void tail_kernel(float* __restrict__ out)
{
    int t = blockIdx.x * blockDim.x + threadIdx.x;   // 0..4095  = b*Hd + h
    int b = t >> 9, h = t & (Hd - 1);
    size_t row = ((size_t)b * S_ + (S_ - 1)) * Hd + h;
    out[NOUT + t]           = g_H0[row];   // layer-0 final state
    out[NOUT + B_ * Hd + t] = out[row];    // layer-1 final state
}

// ---------------- launch ----------------------------------------------------
extern "C" void kernel_launch(void* const* d_in, const int* in_sizes, int n_in,
                              void* d_out, int out_size)
{
    const float* x  = (const float*)d_in[0];
    const float* w0 = (const float*)d_in[1];
    const float* b0 = (const float*)d_in[2];
    const float* w1 = (const float*)d_in[3];
    const float* b1 = (const float*)d_in[4];
    float* out = (float*)d_out;

    dim3 gg(NC / BN, Mrows / BM);

    // layer 0
    sgemm_kernel<<<gg, 256>>>(0, x, w0, b0);
    prep_kernel<<<(Mrows * Hd) / 256, 256>>>();
    scanA_kernel<<<B_ * CH, Hd>>>();
    scanB_kernel<<<B_, Hd>>>();
    scanC_kernel<<<B_ * CH, Hd>>>(0, out);

    // layer 1 (input = g_H0)
    sgemm_kernel<<<gg, 256>>>(1, x, w1, b1);
    prep_kernel<<<(Mrows * Hd) / 256, 256>>>();
    scanA_kernel<<<B_ * CH, Hd>>>();
    scanB_kernel<<<B_, Hd>>>();
    scanC_kernel<<<B_ * CH, Hd>>>(1, out);

    tail_kernel<<<8, 512>>>(out);
}

// round 15
// speedup vs baseline: 1.6921x; 1.6921x over previous
#include <cuda_runtime.h>
#include <cuda_bf16.h>
#include <cstdint>

#define B_    8
#define S_    4096
#define Hd    512
#define KD    512
#define NC    1024
#define Mrows 32768
#define CH    32
#define CL    128
#define NOUT  16777216

// ---------------- scratch (device globals; no allocations allowed) ----------
__device__ __nv_bfloat16 g_Ah0[(size_t)Mrows * KD];   // x hi (layer0 A)
__device__ __nv_bfloat16 g_Al0[(size_t)Mrows * KD];   // x lo
__device__ __nv_bfloat16 g_Ah1[(size_t)Mrows * KD];   // h0 hi (layer1 A)
__device__ __nv_bfloat16 g_Al1[(size_t)Mrows * KD];   // h0 lo
__device__ __nv_bfloat16 g_Wh[2][(size_t)NC * KD];    // W hi, gate/hidden row-interleaved
__device__ __nv_bfloat16 g_Wl[2][(size_t)NC * KD];    // W lo
__device__ float         g_bI[2][NC];                 // bias, interleaved
__device__ float2        g_AV[(size_t)Mrows * Hd];    // (a, v) pairs
__device__ float2        g_carry[B_ * CH * Hd];
__device__ float         g_hstart[B_ * CH * Hd];

// ---------------- PTX helpers (baseline sm_80-class only!) ------------------
__device__ __forceinline__ uint32_t s2u(const void* p) {
    uint32_t a;
    asm("{ .reg .u64 t; cvta.to.shared.u64 t, %1; cvt.u32.u64 %0, t; }" : "=r"(a) : "l"(p));
    return a;
}
__device__ __forceinline__ void cp16(uint32_t s, const void* g) {
    asm volatile("cp.async.cg.shared.global [%0], [%1], 16;" :: "r"(s), "l"(g) : "memory");
}
__device__ __forceinline__ void cp_commit() {
    asm volatile("cp.async.commit_group;" ::: "memory");
}
template <int N> __device__ __forceinline__ void cp_wait() {
    asm volatile("cp.async.wait_group %0;" :: "n"(N) : "memory");
}
__device__ __forceinline__ void ldsm4(uint32_t* d, uint32_t a) {
    asm volatile("ldmatrix.sync.aligned.m8n8.x4.shared.b16 {%0,%1,%2,%3}, [%4];"
                 : "=r"(d[0]), "=r"(d[1]), "=r"(d[2]), "=r"(d[3]) : "r"(a));
}
__device__ __forceinline__ void mma16816(float* c, const uint32_t* a, uint32_t b0, uint32_t b1) {
    asm volatile(
        "mma.sync.aligned.m16n8k16.row.col.f32.bf16.bf16.f32 "
        "{%0,%1,%2,%3}, {%4,%5,%6,%7}, {%8,%9}, {%0,%1,%2,%3};"
        : "+f"(c[0]), "+f"(c[1]), "+f"(c[2]), "+f"(c[3])
        : "r"(a[0]), "r"(a[1]), "r"(a[2]), "r"(a[3]), "r"(b0), "r"(b1));
}
__device__ __forceinline__ uint32_t pkbf(__nv_bfloat16 a, __nv_bfloat16 b) {
    __nv_bfloat162 t; t.x = a; t.y = b;
    return *reinterpret_cast<uint32_t*>(&t);
}

// ---------------- converters ------------------------------------------------
__global__ void convert_x(const float4* __restrict__ x4) {
    size_t i = (size_t)blockIdx.x * blockDim.x + threadIdx.x;   // 4M threads
    float4 v = x4[i];
    __nv_bfloat16 h0 = __float2bfloat16(v.x), h1 = __float2bfloat16(v.y);
    __nv_bfloat16 h2 = __float2bfloat16(v.z), h3 = __float2bfloat16(v.w);
    __nv_bfloat16 l0 = __float2bfloat16(v.x - __bfloat162float(h0));
    __nv_bfloat16 l1 = __float2bfloat16(v.y - __bfloat162float(h1));
    __nv_bfloat16 l2 = __float2bfloat16(v.z - __bfloat162float(h2));
    __nv_bfloat16 l3 = __float2bfloat16(v.w - __bfloat162float(h3));
    reinterpret_cast<uint2*>(g_Ah0)[i] = make_uint2(pkbf(h0, h1), pkbf(h2, h3));
    reinterpret_cast<uint2*>(g_Al0)[i] = make_uint2(pkbf(l0, l1), pkbf(l2, l3));
}

__global__ void convert_w(const float* __restrict__ w0, const float* __restrict__ w1,
                          const float* __restrict__ b0, const float* __restrict__ b1) {
    int idx = blockIdx.x * blockDim.x + threadIdx.x;   // 0 .. 2*1024*128-1
    int l   = idx >> 17;
    int rem = idx & 131071;
    int r   = rem >> 7;      // interleaved dst row 0..1023
    int k4  = rem & 127;
    const float* w = l ? w1 : w0;
    int sr = (r & 1) ? (Hd + (r >> 1)) : (r >> 1);
    float4 v = *reinterpret_cast<const float4*>(w + (size_t)sr * KD + k4 * 4);
    __nv_bfloat16 h0 = __float2bfloat16(v.x), h1 = __float2bfloat16(v.y);
    __nv_bfloat16 h2 = __float2bfloat16(v.z), h3 = __float2bfloat16(v.w);
    __nv_bfloat16 l0 = __float2bfloat16(v.x - __bfloat162float(h0));
    __nv_bfloat16 l1 = __float2bfloat16(v.y - __bfloat162float(h1));
    __nv_bfloat16 l2 = __float2bfloat16(v.z - __bfloat162float(h2));
    __nv_bfloat16 l3 = __float2bfloat16(v.w - __bfloat162float(h3));
    size_t o = (size_t)r * KD + k4 * 4;
    reinterpret_cast<uint2*>(g_Wh[l] + o)[0] = make_uint2(pkbf(h0, h1), pkbf(h2, h3));
    reinterpret_cast<uint2*>(g_Wl[l] + o)[0] = make_uint2(pkbf(l0, l1), pkbf(l2, l3));
    if (k4 == 0) g_bI[l][r] = (l ? b1 : b0)[sr];
}

// ---------------- HMMA GEMM + fused gate epilogue ---------------------------
// C[M=32768, N=1024] over effective K' = 3*512 (bf16 3-split):
//   seg0: Ah*Wh   seg1: Al*Wh   seg2: Ah*Wl
// Tile 128x128, BK=32, 256 threads, 8 warps (2 m x 4 n), warp tile 64x32.
// Smem row stride 80B -> conflict-free ldmatrix without swizzle.
#define NSTG   4
#define KTILES 48
#define ROWB   80                       // bytes per smem row (32 bf16 + 16B pad)
#define OPBYT  (128 * ROWB)             // 10240 per operand
#define STGBYT (2 * OPBYT)              // 20480 per stage
#define SMEM_DYN (NSTG * STGBYT)        // 81920

__global__ void __launch_bounds__(256, 2) gemm_kernel(int layer)
{
    extern __shared__ __align__(1024) char dsm[];
    const uint32_t base = s2u(dsm);

    const int tid  = threadIdx.x;
    const int lane = tid & 31;
    const int wid  = tid >> 5;
    const int wm   = wid & 1;           // 0..1 -> 64 rows each
    const int wn   = wid >> 1;          // 0..3 -> 32 cols each
    const int bn   = blockIdx.x;        // 0..7
    const int bm   = blockIdx.y;        // 0..255

    const __nv_bfloat16* __restrict__ Ah = layer ? g_Ah1 : g_Ah0;
    const __nv_bfloat16* __restrict__ Al = layer ? g_Al1 : g_Al0;
    const __nv_bfloat16* __restrict__ Wh = g_Wh[layer];
    const __nv_bfloat16* __restrict__ Wl = g_Wl[layer];

    // ---- async loader: each thread copies 2x16B of A and 2x16B of B --------
    const int lrow  = tid >> 1;         // 0..127
    const int lhalf = tid & 1;          // which 32B half of the 64B row
    const size_t ga_row = (size_t)(bm * 128 + lrow) * KD;
    const size_t gb_row = (size_t)(bn * 128 + lrow) * KD;
    const uint32_t sa_off = (uint32_t)(lrow * ROWB + lhalf * 32);

    auto load_stage = [&](int kt, int slot) {
        const int seg = kt >> 4, kc = kt & 15;
        const __nv_bfloat16* __restrict__ Ap = (seg == 1) ? Al : Ah;
        const __nv_bfloat16* __restrict__ Bp = (seg == 2) ? Wl : Wh;
        const __nv_bfloat16* ga = Ap + ga_row + kc * 32 + lhalf * 16;
        const __nv_bfloat16* gb = Bp + gb_row + kc * 32 + lhalf * 16;
        uint32_t sa = base + slot * STGBYT + sa_off;
        uint32_t sb = sa + OPBYT;
        cp16(sa,      ga);
        cp16(sa + 16, ga + 8);
        cp16(sb,      gb);
        cp16(sb + 16, gb + 8);
    };

    // ---- per-lane ldmatrix bases -------------------------------------------
    const int lr8 = (lane & 7) + ((lane >> 3) & 1) * 8;   // row within 16-row frag
    const int lc  = (lane >> 4) & 1;                      // k-chunk select
    const uint32_t a_lb = (uint32_t)((wm * 64 + lr8) * ROWB + lc * 16);
    const uint32_t b_lb = (uint32_t)((wn * 32 + lr8) * ROWB + lc * 16) + OPBYT;

    float acc[4][4][4];
#pragma unroll
    for (int i = 0; i < 4; ++i)
#pragma unroll
        for (int j = 0; j < 4; ++j)
#pragma unroll
            for (int q = 0; q < 4; ++q) acc[i][j][q] = 0.0f;

    // ---- pipeline prologue: stages 0..NSTG-2 -------------------------------
#pragma unroll
    for (int p = 0; p < NSTG - 1; ++p) { load_stage(p, p); cp_commit(); }

#pragma unroll 1
    for (int kt = 0; kt < KTILES; ++kt) {
        cp_wait<NSTG - 2>();
        __syncthreads();
        if (kt + NSTG - 1 < KTILES) load_stage(kt + NSTG - 1, (kt + NSTG - 1) & (NSTG - 1));
        cp_commit();

        const uint32_t stg = base + (kt & (NSTG - 1)) * STGBYT;
        const uint32_t abase = stg + a_lb;
        const uint32_t bbase = stg + b_lb;
#pragma unroll
        for (int kf = 0; kf < 2; ++kf) {
            uint32_t afr[4][4], bfr[2][4];
#pragma unroll
            for (int mf = 0; mf < 4; ++mf)
                ldsm4(afr[mf], abase + mf * (16 * ROWB) + kf * 32);
#pragma unroll
            for (int n2 = 0; n2 < 2; ++n2)
                ldsm4(bfr[n2], bbase + n2 * (16 * ROWB) + kf * 32);
#pragma unroll
            for (int mf = 0; mf < 4; ++mf)
#pragma unroll
                for (int nf = 0; nf < 4; ++nf) {
                    const int n2 = nf >> 1, w = nf & 1;
                    mma16816(acc[mf][nf], afr[mf], bfr[n2][w], bfr[n2][w + 2]);
                }
        }
    }

    // ---- fused gate epilogue: (gate, hidden) col pairs -> g_AV (a, v) ------
    const float* __restrict__ bi = g_bI[layer];
    const int nq = lane & 3;                          // quad col
    const int nbase = bn * 128 + wn * 32 + nq * 2;    // interleaved gate col
    float bg[4], bh[4];
#pragma unroll
    for (int nf = 0; nf < 4; ++nf) {
        bg[nf] = bi[nbase + nf * 8];
        bh[nf] = bi[nbase + nf * 8 + 1];
    }
    const int rbase = bm * 128 + wm * 64 + (lane >> 2);
    const int hbase = bn * 64 + wn * 16 + nq;

#pragma unroll
    for (int mf = 0; mf < 4; ++mf)
#pragma unroll
        for (int nf = 0; nf < 4; ++nf) {
#pragma unroll
            for (int half = 0; half < 2; ++half) {
                float ga = acc[mf][nf][2 * half]     + bg[nf];
                float hd = acc[mf][nf][2 * half + 1] + bh[nf];
                float a  = __fdividef(1.0f, 1.0f + __expf(ga));
                float z  = __fdividef(1.0f, 1.0f + __expf(-ga));
                float g  = (hd >= 0.0f) ? (hd + 0.5f)
                                        : __fdividef(1.0f, 1.0f + __expf(-hd));
                int row = rbase + mf * 16 + half * 8;
                g_AV[(size_t)row * Hd + hbase + nf * 4] = make_float2(a, z * g);
            }
        }
}

// ---------------- chunked scan: h_t = a_t*h_{t-1} + v_t,  h_{-1}=0.5 --------
__global__ void scanA_kernel()
{
    int h = threadIdx.x;
    int c = blockIdx.x & (CH - 1);
    int b = blockIdx.x >> 5;
    const float2* p = g_AV + ((size_t)b * S_ + (size_t)c * CL) * Hd + h;
    float P = 1.0f, Q = 0.0f;
#pragma unroll 4
    for (int s = 0; s < CL; ++s) {
        float2 av = p[(size_t)s * Hd];
        Q = fmaf(av.x, Q, av.y);
        P *= av.x;
    }
    g_carry[(b * CH + c) * Hd + h] = make_float2(P, Q);
}

__global__ void scanB_kernel()
{
    int h = threadIdx.x;
    int b = blockIdx.x;
    float2 pq[CH];
#pragma unroll
    for (int c = 0; c < CH; ++c) pq[c] = g_carry[(b * CH + c) * Hd + h];
    float hc = 0.5f;
#pragma unroll
    for (int c = 0; c < CH; ++c) {
        g_hstart[(b * CH + c) * Hd + h] = hc;
        hc = fmaf(pq[c].x, hc, pq[c].y);
    }
}

__global__ void scanC_kernel(int layer, float* __restrict__ Oout)
{
    int h = threadIdx.x;
    int c = blockIdx.x & (CH - 1);
    int b = blockIdx.x >> 5;
    float hc = g_hstart[(b * CH + c) * Hd + h];
    size_t base = ((size_t)b * S_ + (size_t)c * CL) * Hd + h;
    const float2* p = g_AV + base;
    if (layer) {
        float* o = Oout + base;
#pragma unroll 4
        for (int s = 0; s < CL; ++s) {
            float2 av = p[(size_t)s * Hd];
            hc = fmaf(av.x, hc, av.y);
            o[(size_t)s * Hd] = hc;
        }
    } else {
        __nv_bfloat16* oh = g_Ah1 + base;
        __nv_bfloat16* ol = g_Al1 + base;
#pragma unroll 4
        for (int s = 0; s < CL; ++s) {
            float2 av = p[(size_t)s * Hd];
            hc = fmaf(av.x, hc, av.y);
            __nv_bfloat16 hi = __float2bfloat16(hc);
            oh[(size_t)s * Hd] = hi;
            ol[(size_t)s * Hd] = __float2bfloat16(hc - __bfloat162float(hi));
        }
    }
}

// ---------------- tail: stacked next_hidden (2, B, 1, H) --------------------
__global__ void tail_kernel(float* __restrict__ out)
{
    int t = blockIdx.x * blockDim.x + threadIdx.x;   // 0..4095 = b*Hd + h
    int b = t >> 9, h = t & (Hd - 1);
    size_t row = ((size_t)b * S_ + (S_ - 1)) * Hd + h;
    out[NOUT + t] = __bfloat162float(g_Ah1[row]) + __bfloat162float(g_Al1[row]);
    out[NOUT + B_ * Hd + t] = out[row];
}

// ---------------- launch ----------------------------------------------------
extern "C" void kernel_launch(void* const* d_in, const int* in_sizes, int n_in,
                              void* d_out, int out_size)
{
    const float* x  = (const float*)d_in[0];
    const float* w0 = (const float*)d_in[1];
    const float* b0 = (const float*)d_in[2];
    const float* w1 = (const float*)d_in[3];
    const float* b1 = (const float*)d_in[4];
    float* out = (float*)d_out;

    cudaFuncSetAttribute(gemm_kernel, cudaFuncAttributeMaxDynamicSharedMemorySize, SMEM_DYN);

    convert_x<<<16384, 256>>>((const float4*)x);
    convert_w<<<1024, 256>>>(w0, w1, b0, b1);

    dim3 gg(8, 256);   // bn fast: 8 CTAs share each A tile in L2

    // layer 0
    gemm_kernel<<<gg, 256, SMEM_DYN>>>(0);
    scanA_kernel<<<B_ * CH, Hd>>>();
    scanB_kernel<<<B_, Hd>>>();
    scanC_kernel<<<B_ * CH, Hd>>>(0, out);

    // layer 1
    gemm_kernel<<<gg, 256, SMEM_DYN>>>(1);
    scanA_kernel<<<B_ * CH, Hd>>>();
    scanB_kernel<<<B_, Hd>>>();
    scanC_kernel<<<B_ * CH, Hd>>>(1, out);

    tail_kernel<<<8, 512>>>(out);
}